// round 1
// baseline (speedup 1.0000x reference)
#include <cuda_runtime.h>
#include <cuda_bf16.h>
#include <cstdint>

// Problem constants
#define NE   8
#define NT   4096
#define NDIN 2048
#define NDH  1408

// Scratch for intermediate h = silu(x@gate) * (x@down): [E, T, D_H] fp32 (184.5 MB)
__device__ float g_h_scratch[(size_t)NE * NT * NDH];

__device__ __forceinline__ uint32_t f2tf32(float f) {
    uint32_t r;
    asm("cvt.rna.tf32.f32 %0, %1;" : "=r"(r) : "f"(f));
    return r;
}

__device__ __forceinline__ void mma_tf32(float* c, const uint32_t* a, const uint32_t* b) {
    asm volatile(
        "mma.sync.aligned.m16n8k8.row.col.f32.tf32.tf32.f32 "
        "{%0,%1,%2,%3}, {%4,%5,%6,%7}, {%8,%9}, {%0,%1,%2,%3};"
        : "+f"(c[0]), "+f"(c[1]), "+f"(c[2]), "+f"(c[3])
        : "r"(a[0]), "r"(a[1]), "r"(a[2]), "r"(a[3]),
          "r"(b[0]), "r"(b[1]));
}

__device__ __forceinline__ float silu(float x) {
    return x / (1.0f + __expf(-x));
}

// C[e] = A[e] (MxK, row-major) @ B[e] (KxN, row-major)
// MODE 0: C = A@B
// MODE 1: C = silu(G) * (A@B)   (G read at the same addresses as C; in-place safe)
// BM=128, BN=128, BK=16. 256 threads = 8 warps, warp grid 2(m) x 4(n), warp tile 64x32.
template<int MODE>
__global__ __launch_bounds__(256, 2)
void gemm_tf32_kernel(const float* __restrict__ A,
                      const float* __restrict__ B,
                      const float* G,
                      float* C,
                      int M, int N, int K)
{
    // A stored k-major: As[k][m], padded to 132 (fragment LDS conflict-free: bank = 4k+m mod 32)
    // B stored row(k)-major: Bs[k][n], padded to 136 (16B-aligned rows; bank = 8k+n mod 32)
    __shared__ uint32_t As[2][16][132];
    __shared__ uint32_t Bs[2][16][136];

    const int e = blockIdx.z;
    const float* Ae = A + (size_t)e * M * K;
    const float* Be = B + (size_t)e * K * N;
    float*       Ce = C + (size_t)e * M * N;
    const float* Ge = (MODE == 1) ? (G + (size_t)e * M * N) : nullptr;

    const int bm = blockIdx.y * 128;
    const int bn = blockIdx.x * 128;
    const int tid  = threadIdx.x;
    const int lane = tid & 31;
    const int wid  = tid >> 5;
    const int warp_m = wid >> 2;   // 0..1
    const int warp_n = wid & 3;    // 0..3
    const int grp = lane >> 2;     // 0..7
    const int tig = lane & 3;      // 0..3

    // Global->smem load mapping
    const int arow = tid >> 2;     // 0..63  (A rows; second half at +64)
    const int af4  = tid & 3;      // float4 index along K (k = af4*4..af4*4+3)
    const int brow = tid >> 5;     // 0..7   (B k-rows; second half at +8)
    const int bf4  = tid & 31;     // float4 index along N

    const float* aptr0 = Ae + (size_t)(bm + arow) * K + af4 * 4;
    const float* aptr1 = aptr0 + (size_t)64 * K;
    const float* bptr0 = Be + (size_t)brow * N + bn + bf4 * 4;
    const float* bptr1 = bptr0 + (size_t)8 * N;

    float acc[4][4][4];
    #pragma unroll
    for (int i = 0; i < 4; i++)
        #pragma unroll
        for (int j = 0; j < 4; j++)
            #pragma unroll
            for (int k = 0; k < 4; k++)
                acc[i][j][k] = 0.0f;

    // ---- prologue: load tile 0 ----
    {
        float4 a0 = *(const float4*)aptr0;
        float4 a1 = *(const float4*)aptr1;
        float4 b0 = *(const float4*)bptr0;
        float4 b1 = *(const float4*)bptr1;
        const int kb = af4 * 4;
        As[0][kb + 0][arow] = f2tf32(a0.x);
        As[0][kb + 1][arow] = f2tf32(a0.y);
        As[0][kb + 2][arow] = f2tf32(a0.z);
        As[0][kb + 3][arow] = f2tf32(a0.w);
        As[0][kb + 0][arow + 64] = f2tf32(a1.x);
        As[0][kb + 1][arow + 64] = f2tf32(a1.y);
        As[0][kb + 2][arow + 64] = f2tf32(a1.z);
        As[0][kb + 3][arow + 64] = f2tf32(a1.w);
        uint4 tb0 = make_uint4(f2tf32(b0.x), f2tf32(b0.y), f2tf32(b0.z), f2tf32(b0.w));
        uint4 tb1 = make_uint4(f2tf32(b1.x), f2tf32(b1.y), f2tf32(b1.z), f2tf32(b1.w));
        *(uint4*)&Bs[0][brow][bf4 * 4]     = tb0;
        *(uint4*)&Bs[0][brow + 8][bf4 * 4] = tb1;
    }
    __syncthreads();

    const int nk = K >> 4;
    for (int kt = 0; kt < nk; ++kt) {
        const int buf = kt & 1;

        // prefetch next tile into registers
        float4 pa0, pa1, pb0, pb1;
        const bool more = (kt + 1 < nk);
        if (more) {
            aptr0 += 16; aptr1 += 16;
            bptr0 += (size_t)16 * N; bptr1 += (size_t)16 * N;
            pa0 = *(const float4*)aptr0;
            pa1 = *(const float4*)aptr1;
            pb0 = *(const float4*)bptr0;
            pb1 = *(const float4*)bptr1;
        }

        // compute on current buffer: 2 k-steps of 8
        #pragma unroll
        for (int ks = 0; ks < 16; ks += 8) {
            uint32_t af[4][4];
            uint32_t bf[4][2];
            #pragma unroll
            for (int mt = 0; mt < 4; mt++) {
                const int r = warp_m * 64 + mt * 16 + grp;
                af[mt][0] = As[buf][ks + tig][r];
                af[mt][1] = As[buf][ks + tig][r + 8];
                af[mt][2] = As[buf][ks + tig + 4][r];
                af[mt][3] = As[buf][ks + tig + 4][r + 8];
            }
            #pragma unroll
            for (int nt = 0; nt < 4; nt++) {
                const int c = warp_n * 32 + nt * 8 + grp;
                bf[nt][0] = Bs[buf][ks + tig][c];
                bf[nt][1] = Bs[buf][ks + tig + 4][c];
            }
            #pragma unroll
            for (int mt = 0; mt < 4; mt++)
                #pragma unroll
                for (int nt = 0; nt < 4; nt++)
                    mma_tf32(acc[mt][nt], af[mt], bf[nt]);
        }

        // stage prefetched tile
        if (more) {
            const int nb = buf ^ 1;
            const int kb = af4 * 4;
            As[nb][kb + 0][arow] = f2tf32(pa0.x);
            As[nb][kb + 1][arow] = f2tf32(pa0.y);
            As[nb][kb + 2][arow] = f2tf32(pa0.z);
            As[nb][kb + 3][arow] = f2tf32(pa0.w);
            As[nb][kb + 0][arow + 64] = f2tf32(pa1.x);
            As[nb][kb + 1][arow + 64] = f2tf32(pa1.y);
            As[nb][kb + 2][arow + 64] = f2tf32(pa1.z);
            As[nb][kb + 3][arow + 64] = f2tf32(pa1.w);
            uint4 tb0 = make_uint4(f2tf32(pb0.x), f2tf32(pb0.y), f2tf32(pb0.z), f2tf32(pb0.w));
            uint4 tb1 = make_uint4(f2tf32(pb1.x), f2tf32(pb1.y), f2tf32(pb1.z), f2tf32(pb1.w));
            *(uint4*)&Bs[nb][brow][bf4 * 4]     = tb0;
            *(uint4*)&Bs[nb][brow + 8][bf4 * 4] = tb1;
        }
        __syncthreads();
    }

    // ---- epilogue ----
    #pragma unroll
    for (int mt = 0; mt < 4; mt++) {
        #pragma unroll
        for (int nt = 0; nt < 4; nt++) {
            const int row0 = bm + warp_m * 64 + mt * 16 + grp;
            const int col0 = bn + warp_n * 32 + nt * 8 + tig * 2;
            float* p0 = Ce + (size_t)row0 * N + col0;
            float* p1 = p0 + (size_t)8 * N;
            float c0 = acc[mt][nt][0], c1 = acc[mt][nt][1];
            float c2 = acc[mt][nt][2], c3 = acc[mt][nt][3];
            if (MODE == 1) {
                const float* q0 = Ge + (size_t)row0 * N + col0;
                const float* q1 = q0 + (size_t)8 * N;
                float2 gv0 = *(const float2*)q0;
                float2 gv1 = *(const float2*)q1;
                c0 *= silu(gv0.x);
                c1 *= silu(gv0.y);
                c2 *= silu(gv1.x);
                c3 *= silu(gv1.y);
            }
            float2 o0 = make_float2(c0, c1);
            float2 o1 = make_float2(c2, c3);
            *(float2*)p0 = o0;
            *(float2*)p1 = o1;
        }
    }
}

extern "C" void kernel_launch(void* const* d_in, const int* in_sizes, int n_in,
                              void* d_out, int out_size) {
    const float* x    = (const float*)d_in[0];
    const float* gate = (const float*)d_in[1];
    const float* down = (const float*)d_in[2];
    const float* up   = (const float*)d_in[3];
    float* out = (float*)d_out;

    void* sp = nullptr;
    cudaGetSymbolAddress(&sp, g_h_scratch);
    float* h = (float*)sp;

    dim3 blk(256);
    dim3 g12(NDH / 128, NT / 128, NE);   // (11, 32, 8)
    dim3 g3(NDIN / 128, NT / 128, NE);   // (16, 32, 8)

    // 1) G = x @ gate  -> scratch
    gemm_tf32_kernel<0><<<g12, blk>>>(x, gate, nullptr, h, NT, NDH, NDIN);
    // 2) H = silu(G) * (x @ down)  (in-place on scratch)
    gemm_tf32_kernel<1><<<g12, blk>>>(x, down, h, h, NT, NDH, NDIN);
    // 3) out = H @ up
    gemm_tf32_kernel<0><<<g3, blk>>>(h, up, nullptr, out, NT, NDIN, NDH);
}

// round 2
// speedup vs baseline: 1.0011x; 1.0011x over previous
#include <cuda_runtime.h>
#include <cuda_bf16.h>
#include <cstdint>

// Problem constants
#define NE   8
#define NT   4096
#define NDIN 2048
#define NDH  1408

// Scratch for intermediate h = silu(x@gate) * (x@down): [E, T, D_H] fp32 (184.5 MB)
__device__ float g_h_scratch[(size_t)NE * NT * NDH];

__device__ __forceinline__ uint32_t f2tf32(float f) {
    uint32_t r;
    asm("cvt.rna.tf32.f32 %0, %1;" : "=r"(r) : "f"(f));
    return r;
}

__device__ __forceinline__ void mma_tf32(float* c, const uint32_t* a, const uint32_t* b) {
    asm volatile(
        "mma.sync.aligned.m16n8k8.row.col.f32.tf32.tf32.f32 "
        "{%0,%1,%2,%3}, {%4,%5,%6,%7}, {%8,%9}, {%0,%1,%2,%3};"
        : "+f"(c[0]), "+f"(c[1]), "+f"(c[2]), "+f"(c[3])
        : "r"(a[0]), "r"(a[1]), "r"(a[2]), "r"(a[3]),
          "r"(b[0]), "r"(b[1]));
}

__device__ __forceinline__ float silu(float x) {
    return x / (1.0f + __expf(-x));
}

// C[e] = A[e] (MxK, row-major) @ B[e] (KxN, row-major)
// MODE 0: C = A@B
// MODE 1: C = silu(G) * (A@B)   (G read at the same addresses as C; in-place safe)
// BM=128, BN=128, BK=16. 256 threads = 8 warps, warp grid 2(m) x 4(n), warp tile 64x32.
template<int MODE>
__global__ __launch_bounds__(256, 2)
void gemm_tf32_kernel(const float* __restrict__ A,
                      const float* __restrict__ B,
                      const float* G,
                      float* C,
                      int M, int N, int K)
{
    // A stored k-major: As[k][m], padded to 132 (fragment LDS conflict-free: bank = 4k+m mod 32)
    // B stored row(k)-major: Bs[k][n], padded to 136 (16B-aligned rows; bank = 8k+n mod 32)
    __shared__ uint32_t As[2][16][132];
    __shared__ uint32_t Bs[2][16][136];

    const int e = blockIdx.z;
    const float* Ae = A + (size_t)e * M * K;
    const float* Be = B + (size_t)e * K * N;
    float*       Ce = C + (size_t)e * M * N;
    const float* Ge = (MODE == 1) ? (G + (size_t)e * M * N) : nullptr;

    const int bm = blockIdx.y * 128;
    const int bn = blockIdx.x * 128;
    const int tid  = threadIdx.x;
    const int lane = tid & 31;
    const int wid  = tid >> 5;
    const int warp_m = wid >> 2;   // 0..1
    const int warp_n = wid & 3;    // 0..3
    const int grp = lane >> 2;     // 0..7
    const int tig = lane & 3;      // 0..3

    // Global->smem load mapping
    const int arow = tid >> 2;     // 0..63  (A rows; second half at +64)
    const int af4  = tid & 3;      // float4 index along K (k = af4*4..af4*4+3)
    const int brow = tid >> 5;     // 0..7   (B k-rows; second half at +8)
    const int bf4  = tid & 31;     // float4 index along N

    const float* aptr0 = Ae + (size_t)(bm + arow) * K + af4 * 4;
    const float* aptr1 = aptr0 + (size_t)64 * K;
    const float* bptr0 = Be + (size_t)brow * N + bn + bf4 * 4;
    const float* bptr1 = bptr0 + (size_t)8 * N;

    float acc[4][4][4];
    #pragma unroll
    for (int i = 0; i < 4; i++)
        #pragma unroll
        for (int j = 0; j < 4; j++)
            #pragma unroll
            for (int k = 0; k < 4; k++)
                acc[i][j][k] = 0.0f;

    // ---- prologue: load tile 0 ----
    {
        float4 a0 = *(const float4*)aptr0;
        float4 a1 = *(const float4*)aptr1;
        float4 b0 = *(const float4*)bptr0;
        float4 b1 = *(const float4*)bptr1;
        const int kb = af4 * 4;
        As[0][kb + 0][arow] = f2tf32(a0.x);
        As[0][kb + 1][arow] = f2tf32(a0.y);
        As[0][kb + 2][arow] = f2tf32(a0.z);
        As[0][kb + 3][arow] = f2tf32(a0.w);
        As[0][kb + 0][arow + 64] = f2tf32(a1.x);
        As[0][kb + 1][arow + 64] = f2tf32(a1.y);
        As[0][kb + 2][arow + 64] = f2tf32(a1.z);
        As[0][kb + 3][arow + 64] = f2tf32(a1.w);
        uint4 tb0 = make_uint4(f2tf32(b0.x), f2tf32(b0.y), f2tf32(b0.z), f2tf32(b0.w));
        uint4 tb1 = make_uint4(f2tf32(b1.x), f2tf32(b1.y), f2tf32(b1.z), f2tf32(b1.w));
        *(uint4*)&Bs[0][brow][bf4 * 4]     = tb0;
        *(uint4*)&Bs[0][brow + 8][bf4 * 4] = tb1;
    }
    __syncthreads();

    const int nk = K >> 4;
    for (int kt = 0; kt < nk; ++kt) {
        const int buf = kt & 1;

        // prefetch next tile into registers
        float4 pa0, pa1, pb0, pb1;
        const bool more = (kt + 1 < nk);
        if (more) {
            aptr0 += 16; aptr1 += 16;
            bptr0 += (size_t)16 * N; bptr1 += (size_t)16 * N;
            pa0 = *(const float4*)aptr0;
            pa1 = *(const float4*)aptr1;
            pb0 = *(const float4*)bptr0;
            pb1 = *(const float4*)bptr1;
        }

        // compute on current buffer: 2 k-steps of 8
        #pragma unroll
        for (int ks = 0; ks < 16; ks += 8) {
            uint32_t af[4][4];
            uint32_t bf[4][2];
            #pragma unroll
            for (int mt = 0; mt < 4; mt++) {
                const int r = warp_m * 64 + mt * 16 + grp;
                af[mt][0] = As[buf][ks + tig][r];
                af[mt][1] = As[buf][ks + tig][r + 8];
                af[mt][2] = As[buf][ks + tig + 4][r];
                af[mt][3] = As[buf][ks + tig + 4][r + 8];
            }
            #pragma unroll
            for (int nt = 0; nt < 4; nt++) {
                const int c = warp_n * 32 + nt * 8 + grp;
                bf[nt][0] = Bs[buf][ks + tig][c];
                bf[nt][1] = Bs[buf][ks + tig + 4][c];
            }
            #pragma unroll
            for (int mt = 0; mt < 4; mt++)
                #pragma unroll
                for (int nt = 0; nt < 4; nt++)
                    mma_tf32(acc[mt][nt], af[mt], bf[nt]);
        }

        // stage prefetched tile
        if (more) {
            const int nb = buf ^ 1;
            const int kb = af4 * 4;
            As[nb][kb + 0][arow] = f2tf32(pa0.x);
            As[nb][kb + 1][arow] = f2tf32(pa0.y);
            As[nb][kb + 2][arow] = f2tf32(pa0.z);
            As[nb][kb + 3][arow] = f2tf32(pa0.w);
            As[nb][kb + 0][arow + 64] = f2tf32(pa1.x);
            As[nb][kb + 1][arow + 64] = f2tf32(pa1.y);
            As[nb][kb + 2][arow + 64] = f2tf32(pa1.z);
            As[nb][kb + 3][arow + 64] = f2tf32(pa1.w);
            uint4 tb0 = make_uint4(f2tf32(pb0.x), f2tf32(pb0.y), f2tf32(pb0.z), f2tf32(pb0.w));
            uint4 tb1 = make_uint4(f2tf32(pb1.x), f2tf32(pb1.y), f2tf32(pb1.z), f2tf32(pb1.w));
            *(uint4*)&Bs[nb][brow][bf4 * 4]     = tb0;
            *(uint4*)&Bs[nb][brow + 8][bf4 * 4] = tb1;
        }
        __syncthreads();
    }

    // ---- epilogue ----
    #pragma unroll
    for (int mt = 0; mt < 4; mt++) {
        #pragma unroll
        for (int nt = 0; nt < 4; nt++) {
            const int row0 = bm + warp_m * 64 + mt * 16 + grp;
            const int col0 = bn + warp_n * 32 + nt * 8 + tig * 2;
            float* p0 = Ce + (size_t)row0 * N + col0;
            float* p1 = p0 + (size_t)8 * N;
            float c0 = acc[mt][nt][0], c1 = acc[mt][nt][1];
            float c2 = acc[mt][nt][2], c3 = acc[mt][nt][3];
            if (MODE == 1) {
                const float* q0 = Ge + (size_t)row0 * N + col0;
                const float* q1 = q0 + (size_t)8 * N;
                float2 gv0 = *(const float2*)q0;
                float2 gv1 = *(const float2*)q1;
                c0 *= silu(gv0.x);
                c1 *= silu(gv0.y);
                c2 *= silu(gv1.x);
                c3 *= silu(gv1.y);
            }
            float2 o0 = make_float2(c0, c1);
            float2 o1 = make_float2(c2, c3);
            *(float2*)p0 = o0;
            *(float2*)p1 = o1;
        }
    }
}

extern "C" void kernel_launch(void* const* d_in, const int* in_sizes, int n_in,
                              void* d_out, int out_size) {
    const float* x    = (const float*)d_in[0];
    const float* gate = (const float*)d_in[1];
    const float* down = (const float*)d_in[2];
    const float* up   = (const float*)d_in[3];
    float* out = (float*)d_out;

    void* sp = nullptr;
    cudaGetSymbolAddress(&sp, g_h_scratch);
    float* h = (float*)sp;

    dim3 blk(256);
    dim3 g12(NDH / 128, NT / 128, NE);   // (11, 32, 8)
    dim3 g3(NDIN / 128, NT / 128, NE);   // (16, 32, 8)

    // 1) G = x @ gate  -> scratch
    gemm_tf32_kernel<0><<<g12, blk>>>(x, gate, nullptr, h, NT, NDH, NDIN);
    // 2) H = silu(G) * (x @ down)  (in-place on scratch)
    gemm_tf32_kernel<1><<<g12, blk>>>(x, down, h, h, NT, NDH, NDIN);
    // 3) out = H @ up
    gemm_tf32_kernel<0><<<g3, blk>>>(h, up, nullptr, out, NT, NDIN, NDH);
}

// round 4
// speedup vs baseline: 2.9580x; 2.9549x over previous
#include <cuda_runtime.h>
#include <cuda_fp16.h>
#include <cstdint>

#define NE   8
#define NT   4096
#define NDIN 2048
#define NDH  1408

// ---- fp16 scratch ----
__device__ __align__(16) __half g_xh[(size_t)NE * NT * NDIN];    // x fp16, row-major
__device__ __align__(16) __half g_gt[(size_t)NE * NDH * NDIN];   // gate^T  [E][N][K]
__device__ __align__(16) __half g_dt[(size_t)NE * NDH * NDIN];   // down^T  [E][N][K]
__device__ __align__(16) __half g_ut[(size_t)NE * NDIN * NDH];   // up^T    [E][N][K]
__device__ __align__(16) __half g_G [(size_t)NE * NT * NDH];     // x@gate
__device__ __align__(16) __half g_h [(size_t)NE * NT * NDH];     // silu(G)*(x@down)

__device__ __forceinline__ uint32_t smem_u32(const void* p) {
    uint32_t a;
    asm("{ .reg .u64 t; cvta.to.shared.u64 t, %1; cvt.u32.u64 %0, t; }" : "=r"(a) : "l"(p));
    return a;
}

#define CP16(dst, src) \
    asm volatile("cp.async.cg.shared.global [%0], [%1], 16;" :: "r"(dst), "l"(src))
#define CP_COMMIT() asm volatile("cp.async.commit_group;")
#define CP_WAIT2()  asm volatile("cp.async.wait_group 2;")

#define LDSM_X4(r, a) \
    asm volatile("ldmatrix.sync.aligned.m8n8.x4.shared.b16 {%0,%1,%2,%3}, [%4];" \
        : "=r"((r)[0]), "=r"((r)[1]), "=r"((r)[2]), "=r"((r)[3]) : "r"(a))
#define LDSM_X2(r, a) \
    asm volatile("ldmatrix.sync.aligned.m8n8.x2.shared.b16 {%0,%1}, [%2];" \
        : "=r"((r)[0]), "=r"((r)[1]) : "r"(a))

#define HMMA(c, a, b) \
    asm volatile("mma.sync.aligned.m16n8k16.row.col.f32.f16.f16.f32 " \
        "{%0,%1,%2,%3},{%4,%5,%6,%7},{%8,%9},{%0,%1,%2,%3};" \
        : "+f"((c)[0]), "+f"((c)[1]), "+f"((c)[2]), "+f"((c)[3]) \
        : "r"((a)[0]), "r"((a)[1]), "r"((a)[2]), "r"((a)[3]), "r"((b)[0]), "r"((b)[1]))

__device__ __forceinline__ float silu(float x) { return x / (1.0f + __expf(-x)); }

// ---------------- pre-pass: x -> fp16 (same layout) ----------------
__global__ void __launch_bounds__(256) cvt_x(const float4* __restrict__ x, uint2* __restrict__ o) {
    size_t i = (size_t)blockIdx.x * 256 + threadIdx.x;
    float4 v = x[i];
    __half2 a = __floats2half2_rn(v.x, v.y);
    __half2 b = __floats2half2_rn(v.z, v.w);
    uint2 r;
    r.x = *(uint32_t*)&a;
    r.y = *(uint32_t*)&b;
    o[i] = r;
}

// ---------------- pre-pass: W [E][K][N] fp32 -> Wt [E][N][K] fp16 ----------------
__global__ void __launch_bounds__(256) tr_w(const float* __restrict__ W, __half* __restrict__ Wt,
                                            int K, int N) {
    __shared__ float s[64][65];
    const int e = blockIdx.z;
    const int n0 = blockIdx.x * 64;
    const int k0 = blockIdx.y * 64;
    const float* We = W + (size_t)e * K * N;
    __half* Wte = Wt + (size_t)e * K * N;
    const int tx = threadIdx.x & 63, ty = threadIdx.x >> 6;   // ty 0..3
    #pragma unroll
    for (int r = 0; r < 16; r++)
        s[ty * 16 + r][tx] = We[(size_t)(k0 + ty * 16 + r) * N + n0 + tx];
    __syncthreads();
    #pragma unroll
    for (int r = 0; r < 16; r++)
        Wte[(size_t)(n0 + ty * 16 + r) * K + k0 + tx] = __float2half_rn(s[tx][ty * 16 + r]);
}

// ---------------- fp16 HMMA GEMM ----------------
// A: [E][NT][K] fp16 row-major.  Bt: [E][N][K] fp16 row-major.
// MODE 0: C = A@B^T          -> fp16 [E][NT][N]
// MODE 1: C = silu(G)*(A@B^T)-> fp16 [E][NT][N]   (G fp16 same layout)
// MODE 2: C = A@B^T          -> fp32 [E][NT][N]
// BM=BN=128, BK=64. 256 thr = 8 warps (2m x 4n), warp tile 64x32.
template<int MODE>
__global__ void __launch_bounds__(256, 2)
gemm_hmma(const __half* __restrict__ A, const __half* __restrict__ Bt,
          const __half* __restrict__ Gin, void* __restrict__ Cout, int N, int K)
{
    extern __shared__ char sm[];
    const uint32_t sbase = smem_u32(sm);
    const int NK = K >> 6;
    const int e = blockIdx.z, bm = blockIdx.y * 128, bn = blockIdx.x * 128;
    const int tid = threadIdx.x, lane = tid & 31, wid = tid >> 5;

    const char* Ae = (const char*)(A  + ((size_t)e * NT + bm) * K);
    const char* Be = (const char*)(Bt + ((size_t)e * N  + bn) * K);
    const size_t rowstride = (size_t)K * 2;   // bytes per global row

    // stage loader: 128 rows x 8 chunks of 16B for A and B each
    auto stage_load = [&](int kc, int s) {
        if (kc < NK) {
            const uint32_t dA = sbase + s * 32768u;
            const uint32_t dB = dA + 16384u;
            const char* pa = Ae + (size_t)kc * 128;
            const char* pb = Be + (size_t)kc * 128;
            #pragma unroll
            for (int i = 0; i < 4; i++) {
                const int r = i * 32 + (tid >> 3);
                const int c = tid & 7;
                const uint32_t sw = (uint32_t)r * 128 + (uint32_t)((c ^ (r & 7)) << 4);
                const size_t go = (size_t)r * rowstride + c * 16;
                CP16(dA + sw, pa + go);
                CP16(dB + sw, pb + go);
            }
        }
        CP_COMMIT();
    };

    stage_load(0, 0);
    stage_load(1, 1);
    stage_load(2, 2);

    const int wm = (wid >> 2) * 64;    // warp m offset
    const int wn = (wid & 3) * 32;     // warp n offset
    const int grp = lane >> 2, tig = lane & 3;
    const int hiA = lane >> 4;             // 0/1
    const int hiB = (lane >> 3) & 1;       // 0/1
    const int s7  = lane & 7;              // row&7 for both A and B lanes

    float acc[4][4][4];
    #pragma unroll
    for (int i = 0; i < 4; i++)
        #pragma unroll
        for (int j = 0; j < 4; j++)
            #pragma unroll
            for (int q = 0; q < 4; q++)
                acc[i][j][q] = 0.0f;

    for (int kc = 0; kc < NK; kc++) {
        const int s = kc % 3;
        CP_WAIT2();
        __syncthreads();

        const uint32_t sA = sbase + s * 32768u;
        const uint32_t sB = sA + 16384u;
        const uint32_t aBase = sA + (uint32_t)(wm + (lane & 15)) * 128;
        const uint32_t bBase = sB + (uint32_t)(wn + (lane & 7)) * 128;

        #pragma unroll
        for (int ks = 0; ks < 4; ks++) {
            uint32_t af[4][4], bf[4][2];
            const uint32_t ca = (uint32_t)(((ks * 2 + hiA) ^ s7) << 4);
            const uint32_t cb = (uint32_t)(((ks * 2 + hiB) ^ s7) << 4);
            #pragma unroll
            for (int mt = 0; mt < 4; mt++)
                LDSM_X4(af[mt], aBase + (uint32_t)mt * 2048 + ca);
            #pragma unroll
            for (int nt = 0; nt < 4; nt++)
                LDSM_X2(bf[nt], bBase + (uint32_t)nt * 1024 + cb);
            #pragma unroll
            for (int mt = 0; mt < 4; mt++)
                #pragma unroll
                for (int nt = 0; nt < 4; nt++)
                    HMMA(acc[mt][nt], af[mt], bf[nt]);
        }

        __syncthreads();
        stage_load(kc + 3, s);
    }

    // ---------------- epilogue ----------------
    #pragma unroll
    for (int mt = 0; mt < 4; mt++) {
        #pragma unroll
        for (int nt = 0; nt < 4; nt++) {
            const int row0 = bm + wm + mt * 16 + grp;
            const int col0 = bn + wn + nt * 8 + tig * 2;
            float c0 = acc[mt][nt][0], c1 = acc[mt][nt][1];
            float c2 = acc[mt][nt][2], c3 = acc[mt][nt][3];
            if (MODE == 2) {
                float* out = (float*)Cout + ((size_t)e * NT + row0) * N + col0;
                *(float2*)out = make_float2(c0, c1);
                *(float2*)(out + (size_t)8 * N) = make_float2(c2, c3);
            } else {
                if (MODE == 1) {
                    const __half* Ge = Gin + ((size_t)e * NT + row0) * N + col0;
                    __half2 g0 = *(const __half2*)Ge;
                    __half2 g1 = *(const __half2*)(Ge + (size_t)8 * N);
                    c0 *= silu(__low2float(g0));
                    c1 *= silu(__high2float(g0));
                    c2 *= silu(__low2float(g1));
                    c3 *= silu(__high2float(g1));
                }
                __half* out = (__half*)Cout + ((size_t)e * NT + row0) * N + col0;
                __half2 o0 = __floats2half2_rn(c0, c1);
                __half2 o1 = __floats2half2_rn(c2, c3);
                *(__half2*)out = o0;
                *(__half2*)(out + (size_t)8 * N) = o1;
            }
        }
    }
}

// ---------------- host ----------------
extern "C" void kernel_launch(void* const* d_in, const int* in_sizes, int n_in,
                              void* d_out, int out_size) {
    const float* x    = (const float*)d_in[0];
    const float* gate = (const float*)d_in[1];
    const float* down = (const float*)d_in[2];
    const float* up   = (const float*)d_in[3];
    float* out = (float*)d_out;

    void *xh, *gt, *dt, *ut, *Gp, *hp;
    cudaGetSymbolAddress(&xh, g_xh);
    cudaGetSymbolAddress(&gt, g_gt);
    cudaGetSymbolAddress(&dt, g_dt);
    cudaGetSymbolAddress(&ut, g_ut);
    cudaGetSymbolAddress(&Gp, g_G);
    cudaGetSymbolAddress(&hp, g_h);

    const int SMEM = 3 * 32768;   // 96 KB
    cudaFuncSetAttribute(gemm_hmma<0>, cudaFuncAttributeMaxDynamicSharedMemorySize, SMEM);
    cudaFuncSetAttribute(gemm_hmma<1>, cudaFuncAttributeMaxDynamicSharedMemorySize, SMEM);
    cudaFuncSetAttribute(gemm_hmma<2>, cudaFuncAttributeMaxDynamicSharedMemorySize, SMEM);

    // pre-passes
    cvt_x<<<(NE * NT * NDIN / 4) / 256, 256>>>((const float4*)x, (uint2*)xh);
    tr_w<<<dim3(NDH / 64, NDIN / 64, NE), 256>>>(gate, (__half*)gt, NDIN, NDH);
    tr_w<<<dim3(NDH / 64, NDIN / 64, NE), 256>>>(down, (__half*)dt, NDIN, NDH);
    tr_w<<<dim3(NDIN / 64, NDH / 64, NE), 256>>>(up,   (__half*)ut, NDH, NDIN);

    dim3 blk(256);
    dim3 g12(NDH / 128, NT / 128, NE);   // (11, 32, 8)
    dim3 g3(NDIN / 128, NT / 128, NE);   // (16, 32, 8)

    // 1) G = x @ gate^T
    gemm_hmma<0><<<g12, blk, SMEM>>>((const __half*)xh, (const __half*)gt, nullptr, Gp, NDH, NDIN);
    // 2) h = silu(G) * (x @ down^T)
    gemm_hmma<1><<<g12, blk, SMEM>>>((const __half*)xh, (const __half*)dt, (const __half*)Gp, hp, NDH, NDIN);
    // 3) out = h @ up^T   (fp32 out)
    gemm_hmma<2><<<g3, blk, SMEM>>>((const __half*)hp, (const __half*)ut, nullptr, out, NDIN, NDH);
}

// round 6
// speedup vs baseline: 2.9923x; 1.0116x over previous
#include <cuda_runtime.h>
#include <cuda_fp16.h>
#include <cstdint>

#define NE   8
#define NT   4096
#define NDIN 2048
#define NDH  1408

// ---- fp16 scratch ----
__device__ __align__(16) __half g_xh[(size_t)NE * NT * NDIN];    // x fp16, row-major
__device__ __align__(16) __half g_gt[(size_t)NE * NDH * NDIN];   // gate^T  [E][N][K]
__device__ __align__(16) __half g_dt[(size_t)NE * NDH * NDIN];   // down^T  [E][N][K]
__device__ __align__(16) __half g_ut[(size_t)NE * NDIN * NDH];   // up^T    [E][N][K]
__device__ __align__(16) __half g_h [(size_t)NE * NT * NDH];     // silu(x@g)*(x@d)

__device__ __forceinline__ uint32_t smem_u32(const void* p) {
    uint32_t a;
    asm("{ .reg .u64 t; cvta.to.shared.u64 t, %1; cvt.u32.u64 %0, t; }" : "=r"(a) : "l"(p));
    return a;
}

#define CP16(dst, src) \
    asm volatile("cp.async.cg.shared.global [%0], [%1], 16;" :: "r"(dst), "l"(src))
#define CP_COMMIT() asm volatile("cp.async.commit_group;")
#define CP_WAITG(n) asm volatile("cp.async.wait_group %0;" :: "n"(n))

#define LDSM_X4(r, a) \
    asm volatile("ldmatrix.sync.aligned.m8n8.x4.shared.b16 {%0,%1,%2,%3}, [%4];" \
        : "=r"((r)[0]), "=r"((r)[1]), "=r"((r)[2]), "=r"((r)[3]) : "r"(a))
#define LDSM_X2(r, a) \
    asm volatile("ldmatrix.sync.aligned.m8n8.x2.shared.b16 {%0,%1}, [%2];" \
        : "=r"((r)[0]), "=r"((r)[1]) : "r"(a))

#define HMMA(c, a, b) \
    asm volatile("mma.sync.aligned.m16n8k16.row.col.f32.f16.f16.f32 " \
        "{%0,%1,%2,%3},{%4,%5,%6,%7},{%8,%9},{%0,%1,%2,%3};" \
        : "+f"((c)[0]), "+f"((c)[1]), "+f"((c)[2]), "+f"((c)[3]) \
        : "r"((a)[0]), "r"((a)[1]), "r"((a)[2]), "r"((a)[3]), "r"((b)[0]), "r"((b)[1]))

__device__ __forceinline__ float silu(float x) { return x / (1.0f + __expf(-x)); }

// ---------------- pre-pass: x -> fp16 ----------------
__global__ void __launch_bounds__(256) cvt_x(const float4* __restrict__ x, uint2* __restrict__ o) {
    size_t i = (size_t)blockIdx.x * 256 + threadIdx.x;
    float4 v = x[i];
    __half2 a = __floats2half2_rn(v.x, v.y);
    __half2 b = __floats2half2_rn(v.z, v.w);
    uint2 r;
    r.x = *(uint32_t*)&a;
    r.y = *(uint32_t*)&b;
    o[i] = r;
}

// ---------------- pre-pass: W [E][K][N] fp32 -> Wt [E][N][K] fp16 ----------------
__global__ void __launch_bounds__(256) tr_w(const float* __restrict__ W, __half* __restrict__ Wt,
                                            int K, int N) {
    __shared__ float s[64][65];
    const int e = blockIdx.z;
    const int n0 = blockIdx.x * 64;
    const int k0 = blockIdx.y * 64;
    const float* We = W + (size_t)e * K * N;
    __half* Wte = Wt + (size_t)e * K * N;
    const int tx = threadIdx.x & 63, ty = threadIdx.x >> 6;
    #pragma unroll
    for (int r = 0; r < 16; r++)
        s[ty * 16 + r][tx] = We[(size_t)(k0 + ty * 16 + r) * N + n0 + tx];
    __syncthreads();
    #pragma unroll
    for (int r = 0; r < 16; r++)
        Wte[(size_t)(n0 + ty * 16 + r) * K + k0 + tx] = __float2half_rn(s[tx][ty * 16 + r]);
}

// ---------------- fused GEMM1+2: h = silu(x@gate^T) * (x@down^T) ----------------
// A [E][NT][K] fp16, Bg/Bd [E][N][K] fp16. BM=BN=128, BK=64, 4-stage (48KB each).
__global__ void __launch_bounds__(256, 1)
gemm_fused(const __half* __restrict__ A, const __half* __restrict__ Bg,
           const __half* __restrict__ Bd, __half* __restrict__ H, int N, int K)
{
    extern __shared__ char sm[];
    const uint32_t sbase = smem_u32(sm);
    const int NK = K >> 6;                 // 32
    const int e = blockIdx.z, bm = blockIdx.y * 128, bn = blockIdx.x * 128;
    const int tid = threadIdx.x, lane = tid & 31, wid = tid >> 5;

    const char* Ae  = (const char*)(A  + ((size_t)e * NT + bm) * K);
    const char* Bge = (const char*)(Bg + ((size_t)e * N  + bn) * K);
    const char* Bde = (const char*)(Bd + ((size_t)e * N  + bn) * K);
    const size_t rowstride = (size_t)K * 2;

    auto stage_load = [&](int kc, int s) {
        if (kc < NK) {
            const uint32_t d = sbase + (uint32_t)s * 49152u;
            const char* pa = Ae  + (size_t)kc * 128;
            const char* pg = Bge + (size_t)kc * 128;
            const char* pd = Bde + (size_t)kc * 128;
            #pragma unroll
            for (int i = 0; i < 4; i++) {
                const int r = i * 32 + (tid >> 3);
                const int c = tid & 7;
                const uint32_t sw = (uint32_t)r * 128 + (uint32_t)((c ^ (r & 7)) << 4);
                const size_t go = (size_t)r * rowstride + c * 16;
                CP16(d + sw,          pa + go);
                CP16(d + 16384u + sw, pg + go);
                CP16(d + 32768u + sw, pd + go);
            }
        }
        CP_COMMIT();
    };

    stage_load(0, 0);
    stage_load(1, 1);
    stage_load(2, 2);

    const int wm = (wid >> 2) * 64;
    const int wn = (wid & 3) * 32;
    const int grp = lane >> 2, tig = lane & 3;
    const int hiA = lane >> 4;
    const int hiB = (lane >> 3) & 1;
    const int s7  = lane & 7;

    float ag[4][4][4], ad_[4][4][4];
    #pragma unroll
    for (int i = 0; i < 4; i++)
        #pragma unroll
        for (int j = 0; j < 4; j++)
            #pragma unroll
            for (int q = 0; q < 4; q++) { ag[i][j][q] = 0.0f; ad_[i][j][q] = 0.0f; }

    for (int kc = 0; kc < NK; kc++) {
        const int s = kc & 3;
        CP_WAITG(2);
        __syncthreads();

        const uint32_t sA  = sbase + (uint32_t)s * 49152u;
        const uint32_t aBase  = sA + (uint32_t)(wm + (lane & 15)) * 128;
        const uint32_t bgBase = sA + 16384u + (uint32_t)(wn + (lane & 7)) * 128;
        const uint32_t bdBase = sA + 32768u + (uint32_t)(wn + (lane & 7)) * 128;

        #pragma unroll
        for (int ks = 0; ks < 4; ks++) {
            uint32_t af[4][4], bg[4][2], bd[4][2];
            const uint32_t ca = (uint32_t)(((ks * 2 + hiA) ^ s7) << 4);
            const uint32_t cb = (uint32_t)(((ks * 2 + hiB) ^ s7) << 4);
            #pragma unroll
            for (int mt = 0; mt < 4; mt++)
                LDSM_X4(af[mt], aBase + (uint32_t)mt * 2048 + ca);
            #pragma unroll
            for (int nt = 0; nt < 4; nt++) {
                LDSM_X2(bg[nt], bgBase + (uint32_t)nt * 1024 + cb);
                LDSM_X2(bd[nt], bdBase + (uint32_t)nt * 1024 + cb);
            }
            #pragma unroll
            for (int mt = 0; mt < 4; mt++)
                #pragma unroll
                for (int nt = 0; nt < 4; nt++) {
                    HMMA(ag[mt][nt],  af[mt], bg[nt]);
                    HMMA(ad_[mt][nt], af[mt], bd[nt]);
                }
        }

        __syncthreads();
        stage_load(kc + 3, (kc + 3) & 3);   // FIX: correct ring slot for tile kc+3
    }

    // epilogue: h = silu(g) * d, fp16
    #pragma unroll
    for (int mt = 0; mt < 4; mt++) {
        #pragma unroll
        for (int nt = 0; nt < 4; nt++) {
            const int row0 = bm + wm + mt * 16 + grp;
            const int col0 = bn + wn + nt * 8 + tig * 2;
            float h0 = silu(ag[mt][nt][0]) * ad_[mt][nt][0];
            float h1 = silu(ag[mt][nt][1]) * ad_[mt][nt][1];
            float h2 = silu(ag[mt][nt][2]) * ad_[mt][nt][2];
            float h3 = silu(ag[mt][nt][3]) * ad_[mt][nt][3];
            __half* out = H + ((size_t)e * NT + row0) * N + col0;
            *(__half2*)out = __floats2half2_rn(h0, h1);
            *(__half2*)(out + (size_t)8 * N) = __floats2half2_rn(h2, h3);
        }
    }
}

// ---------------- GEMM3: out = h @ up^T (fp32 out) ----------------
__global__ void __launch_bounds__(256, 2)
gemm_hmma(const __half* __restrict__ A, const __half* __restrict__ Bt,
          float* __restrict__ Cout, int N, int K)
{
    extern __shared__ char sm[];
    const uint32_t sbase = smem_u32(sm);
    const int NK = K >> 6;
    const int e = blockIdx.z, bm = blockIdx.y * 128, bn = blockIdx.x * 128;
    const int tid = threadIdx.x, lane = tid & 31, wid = tid >> 5;

    const char* Ae = (const char*)(A  + ((size_t)e * NT + bm) * K);
    const char* Be = (const char*)(Bt + ((size_t)e * N  + bn) * K);
    const size_t rowstride = (size_t)K * 2;

    auto stage_load = [&](int kc, int s) {
        if (kc < NK) {
            const uint32_t dA = sbase + s * 32768u;
            const uint32_t dB = dA + 16384u;
            const char* pa = Ae + (size_t)kc * 128;
            const char* pb = Be + (size_t)kc * 128;
            #pragma unroll
            for (int i = 0; i < 4; i++) {
                const int r = i * 32 + (tid >> 3);
                const int c = tid & 7;
                const uint32_t sw = (uint32_t)r * 128 + (uint32_t)((c ^ (r & 7)) << 4);
                const size_t go = (size_t)r * rowstride + c * 16;
                CP16(dA + sw, pa + go);
                CP16(dB + sw, pb + go);
            }
        }
        CP_COMMIT();
    };

    stage_load(0, 0);
    stage_load(1, 1);
    stage_load(2, 2);

    const int wm = (wid >> 2) * 64;
    const int wn = (wid & 3) * 32;
    const int grp = lane >> 2, tig = lane & 3;
    const int hiA = lane >> 4;
    const int hiB = (lane >> 3) & 1;
    const int s7  = lane & 7;

    float acc[4][4][4];
    #pragma unroll
    for (int i = 0; i < 4; i++)
        #pragma unroll
        for (int j = 0; j < 4; j++)
            #pragma unroll
            for (int q = 0; q < 4; q++)
                acc[i][j][q] = 0.0f;

    for (int kc = 0; kc < NK; kc++) {
        const int s = kc % 3;
        CP_WAITG(2);
        __syncthreads();

        const uint32_t sA = sbase + s * 32768u;
        const uint32_t sB = sA + 16384u;
        const uint32_t aBase = sA + (uint32_t)(wm + (lane & 15)) * 128;
        const uint32_t bBase = sB + (uint32_t)(wn + (lane & 7)) * 128;

        #pragma unroll
        for (int ks = 0; ks < 4; ks++) {
            uint32_t af[4][4], bf[4][2];
            const uint32_t ca = (uint32_t)(((ks * 2 + hiA) ^ s7) << 4);
            const uint32_t cb = (uint32_t)(((ks * 2 + hiB) ^ s7) << 4);
            #pragma unroll
            for (int mt = 0; mt < 4; mt++)
                LDSM_X4(af[mt], aBase + (uint32_t)mt * 2048 + ca);
            #pragma unroll
            for (int nt = 0; nt < 4; nt++)
                LDSM_X2(bf[nt], bBase + (uint32_t)nt * 1024 + cb);
            #pragma unroll
            for (int mt = 0; mt < 4; mt++)
                #pragma unroll
                for (int nt = 0; nt < 4; nt++)
                    HMMA(acc[mt][nt], af[mt], bf[nt]);
        }

        __syncthreads();
        stage_load(kc + 3, (kc + 3) % 3);
    }

    #pragma unroll
    for (int mt = 0; mt < 4; mt++) {
        #pragma unroll
        for (int nt = 0; nt < 4; nt++) {
            const int row0 = bm + wm + mt * 16 + grp;
            const int col0 = bn + wn + nt * 8 + tig * 2;
            float* out = Cout + ((size_t)e * NT + row0) * N + col0;
            *(float2*)out = make_float2(acc[mt][nt][0], acc[mt][nt][1]);
            *(float2*)(out + (size_t)8 * N) = make_float2(acc[mt][nt][2], acc[mt][nt][3]);
        }
    }
}

// ---------------- host ----------------
extern "C" void kernel_launch(void* const* d_in, const int* in_sizes, int n_in,
                              void* d_out, int out_size) {
    const float* x    = (const float*)d_in[0];
    const float* gate = (const float*)d_in[1];
    const float* down = (const float*)d_in[2];
    const float* up   = (const float*)d_in[3];
    float* out = (float*)d_out;

    void *xh, *gt, *dt, *ut, *hp;
    cudaGetSymbolAddress(&xh, g_xh);
    cudaGetSymbolAddress(&gt, g_gt);
    cudaGetSymbolAddress(&dt, g_dt);
    cudaGetSymbolAddress(&ut, g_ut);
    cudaGetSymbolAddress(&hp, g_h);

    const int SMEM_F = 4 * 49152;   // 192 KB
    const int SMEM_3 = 3 * 32768;   // 96 KB
    cudaFuncSetAttribute(gemm_fused, cudaFuncAttributeMaxDynamicSharedMemorySize, SMEM_F);
    cudaFuncSetAttribute(gemm_hmma,  cudaFuncAttributeMaxDynamicSharedMemorySize, SMEM_3);

    // pre-passes
    cvt_x<<<(NE * NT * NDIN / 4) / 256, 256>>>((const float4*)x, (uint2*)xh);
    tr_w<<<dim3(NDH / 64, NDIN / 64, NE), 256>>>(gate, (__half*)gt, NDIN, NDH);
    tr_w<<<dim3(NDH / 64, NDIN / 64, NE), 256>>>(down, (__half*)dt, NDIN, NDH);
    tr_w<<<dim3(NDIN / 64, NDH / 64, NE), 256>>>(up,   (__half*)ut, NDH, NDIN);

    // fused: h = silu(x@gate^T) * (x@down^T)
    gemm_fused<<<dim3(NDH / 128, NT / 128, NE), 256, SMEM_F>>>(
        (const __half*)xh, (const __half*)gt, (const __half*)dt, (__half*)hp, NDH, NDIN);
    // out = h @ up^T
    gemm_hmma<<<dim3(NDIN / 128, NT / 128, NE), 256, SMEM_3>>>(
        (const __half*)hp, (const __half*)ut, out, NDIN, NDH);
}